// round 12
// baseline (speedup 1.0000x reference)
#include <cuda_runtime.h>
#include <cstdint>

// Problem dims
#define HWX  16384      // 128*128
#define CHWX 1048576    // 64*128*128
#define TOTX 8388608    // 8*64*128*128

typedef unsigned long long ull;

// ---------------- device scratch (allocation-free rule: device globals) ----
__device__ __align__(16) float g_hs [TOTX];   // south row-scan, natural [b][c][h][w]
__device__ __align__(16) float g_hn [TOTX];   // north row-scan, natural
__device__ __align__(16) float g_hsT[TOTX];   // [b][c][w][h]
__device__ __align__(16) float g_hnT[TOTX];
__device__ __align__(16) float g_yT [TOTX];   // y transposed [b][c][w][h]
__device__ __align__(16) float g_col[4][TOTX];// per-direction col-scan output, [b][c][w][h]

// ---------------- f32x2 helpers -------------------------------------------
__device__ __forceinline__ ull dup2(float w) {
    ull r; asm("mov.b64 %0, {%1, %1};" : "=l"(r) : "f"(w)); return r;
}
__device__ __forceinline__ void fma2(ull& acc, ull a, ull b) {
    asm("fma.rn.f32x2 %0, %1, %2, %0;" : "+l"(acc) : "l"(a), "l"(b));
}
__device__ __forceinline__ float2 unpk(ull v) {
    float2 f; asm("mov.b64 {%0, %1}, %2;" : "=f"(f.x), "=f"(f.y) : "l"(v)); return f;
}
__device__ __forceinline__ ull dal(double d) { return __double_as_longlong(d); }

// ---------------- cp.async helpers ----------------------------------------
__device__ __forceinline__ void cpasync16(void* s, const void* g) {
    uint32_t sa = (uint32_t)__cvta_generic_to_shared(s);
    asm volatile("cp.async.ca.shared.global [%0], [%1], 16;" :: "r"(sa), "l"(g) : "memory");
}
__device__ __forceinline__ void cpcommit() { asm volatile("cp.async.commit_group;" ::: "memory"); }
__device__ __forceinline__ void cpwait0()  { asm volatile("cp.async.wait_group 0;"  ::: "memory"); }

// DSMEM scalar store into peer CTA's shared memory (cluster rank `rank`)
__device__ __forceinline__ void dsmem_store(float* laddr, int rank, float v) {
    uint32_t la = (uint32_t)__cvta_generic_to_shared(laddr);
    uint32_t ra;
    asm volatile("mapa.shared::cluster.u32 %0, %1, %2;" : "=r"(ra) : "r"(la), "r"(rank));
    asm volatile("st.shared::cluster.f32 [%0], %1;" :: "r"(ra), "f"(v) : "memory");
}

__device__ __forceinline__ float4 relu4(float4 v) {
    v.x = fmaxf(v.x, 0.f); v.y = fmaxf(v.y, 0.f);
    v.z = fmaxf(v.z, 0.f); v.w = fmaxf(v.w, 0.f);
    return v;
}

extern __shared__ __align__(16) float smdyn[];

// ===========================================================================
// Kernel 1: row scans (south dir=0, north dir=1).  [identical to 713us build]
// grid (8 w-tiles, 8 batch, 2 dirs), 128 threads.
// Thread tile: 4 o x 2 w (one f32x2 pair). Weights [c][o] float2 + dup2.
// x/y tiles double-buffered via cp.async.
// smem (floats): WaT 0, WbT 4096, sx 8192(2x1024), sy 10240(2x1024),
//                sh 12288, ba 13312, bb 13376  -> 13440 fl = 53760 B
// ===========================================================================
__global__ void __launch_bounds__(128, 1) row_scan_kernel(
    const float* __restrict__ x, const float* __restrict__ y,
    const float* __restrict__ Wc, const float* __restrict__ bc)
{
    float* sWaT = smdyn;
    float* sWbT = smdyn + 4096;
    float* sx   = smdyn + 8192;
    float* sy   = smdyn + 10240;
    float* sh   = smdyn + 12288;
    float* sba  = smdyn + 13312;
    float* sbb  = smdyn + 13376;

    const int dir = blockIdx.z;          // 0 = south, 1 = north
    const int b   = blockIdx.y;
    const int w0  = blockIdx.x * 16;
    const int t   = threadIdx.x;

    const int ka = dir ? 8 : 0;
    const float* Wa = Wc + ka * 4096;
    const float* Wb = Wc + (ka + 1) * 4096;
    for (int idx = t; idx < 4096; idx += 128) {
        int o = idx >> 6, c = idx & 63;
        sWaT[c * 64 + o] = Wa[idx];
        sWbT[c * 64 + o] = Wb[idx];
    }
    if (t < 64) { sba[t] = bc[ka * 64 + t]; sbb[t] = bc[(ka + 1) * 64 + t]; }

    const float* xb = x + b * CHWX + w0;
    const float* yb = y + b * CHWX + w0;
    float* hb = (dir ? g_hn : g_hs) + b * CHWX + w0;

    // boundary row init: 8 floats per thread
    {
        const int r0 = dir ? 127 : 0;
        const int c  = t >> 1;
        const int wv = (t & 1) * 8;
        #pragma unroll
        for (int kk = 0; kk < 2; ++kk) {
            float4 v = *(const float4*)(xb + c * HWX + r0 * 128 + wv + kk * 4);
            if (dir) v = relu4(v);
            *(float4*)(sh + c * 16 + wv + kk * 4) = v;
            *(float4*)(hb + c * HWX + r0 * 128 + wv + kk * 4) = v;
        }
    }
    // prefetch step 1 tiles into parity-1 buffers
    {
        const int r2  = dir ? 126 : 1;
        const int yr2 = dir ? 127 : 0;
        #pragma unroll
        for (int k = 0; k < 2; ++k) {
            int q = t + 128 * k;
            int c = q >> 2, w = (q & 3) * 4;
            cpasync16(sx + 1024 + c * 16 + w, xb + c * HWX + r2  * 128 + w);
            cpasync16(sy + 1024 + c * 16 + w, yb + c * HWX + yr2 * 128 + w);
        }
        cpcommit();
    }

    const int o4 = (t >> 3) * 4;         // 4 out-channels
    const int wq = (t & 7) * 2;          // one w pair

    for (int i = 1; i < 128; ++i) {
        const int p = i & 1;
        const float* sxP = sx + p * 1024;
        const float* syP = sy + p * 1024;
        const int r = dir ? 127 - i : i;

        cpwait0();
        __syncthreads();

        if (i < 127) {
            const int r2  = dir ? 127 - (i + 1) : (i + 1);
            const int yr2 = dir ? r2 + 1 : r2 - 1;
            float* sxN = sx + (1 - p) * 1024;
            float* syN = sy + (1 - p) * 1024;
            #pragma unroll
            for (int k = 0; k < 2; ++k) {
                int q = t + 128 * k;
                int c = q >> 2, w = (q & 3) * 4;
                cpasync16(sxN + c * 16 + w, xb + c * HWX + r2  * 128 + w);
                cpasync16(syN + c * 16 + w, yb + c * HWX + yr2 * 128 + w);
            }
            cpcommit();
        }

        ull aa[4], ab[4];
        #pragma unroll
        for (int k = 0; k < 4; ++k) { aa[k] = 0ULL; ab[k] = 0ULL; }

        #pragma unroll 4
        for (int c = 0; c < 64; ++c) {
            ull xv = dal(*(const double*)(sxP + c * 16 + wq));
            ull hv = dal(*(const double*)(sh  + c * 16 + wq));
            float4 wa = *(const float4*)(sWaT + c * 64 + o4);
            float4 wb = *(const float4*)(sWbT + c * 64 + o4);
            float wa4[4] = {wa.x, wa.y, wa.z, wa.w};
            float wb4[4] = {wb.x, wb.y, wb.z, wb.w};
            #pragma unroll
            for (int k = 0; k < 4; ++k) {
                fma2(aa[k], xv, dup2(wa4[k]));
                fma2(ab[k], hv, dup2(wb4[k]));
            }
        }

        float2 res[4];
        #pragma unroll
        for (int k = 0; k < 4; ++k) {
            const int o = o4 + k;
            float2 A  = unpk(aa[k]);
            float2 Bv = unpk(ab[k]);
            float2 yv = *(const float2*)(syP + o * 16 + wq);
            const float ba_ = sba[o], bb_ = sbb[o];
            res[k].x = fmaxf(A.x + ba_ + (Bv.x + bb_) * yv.x, 0.f);
            res[k].y = fmaxf(A.y + ba_ + (Bv.y + bb_) * yv.y, 0.f);
        }
        __syncthreads();
        #pragma unroll
        for (int k = 0; k < 4; ++k) {
            const int o = o4 + k;
            *(float2*)(sh + o * 16 + wq) = res[k];
            *(float2*)(hb + o * HWX + r * 128 + wq) = res[k];
        }
    }
}

// ===========================================================================
// Kernel 2: batched 128x128 transpose of last two dims.
// blockIdx.z: [0,512)=y->yT, [512,1024)=hs->hsT, [1024,1536)=hn->hnT
// ===========================================================================
__global__ void __launch_bounds__(256, 1) transpose3_kernel(const float* __restrict__ ysrc)
{
    __shared__ float tile[32][33];
    const int mode = blockIdx.z >> 9;
    const int n    = blockIdx.z & 511;
    const float* src = (mode == 0 ? ysrc : (mode == 1 ? g_hs : g_hn)) + n * HWX;
    float*       dst = (mode == 0 ? g_yT : (mode == 1 ? g_hsT : g_hnT)) + n * HWX;
    const int r0 = blockIdx.y * 32, c0 = blockIdx.x * 32;
    const int tx = threadIdx.x & 31, ty = (threadIdx.x >> 5) * 4;
    #pragma unroll
    for (int k = 0; k < 4; ++k) tile[ty + k][tx] = src[(r0 + ty + k) * 128 + c0 + tx];
    __syncthreads();
    #pragma unroll
    for (int k = 0; k < 4; ++k) dst[(c0 + ty + k) * 128 + r0 + tx] = tile[tx][ty + k];
}

// ===========================================================================
// Kernel 3: column scans, all 4 directions in one launch.
// grid (4 H-chunks [cluster 4], 8 batch, 4 dirs), 128 threads.
// Identical to the 713us build EXCEPT: the cluster barrier is split into
// arrive/wait, and the halo-independent epilogue half (A + ba + (B+bb)*y)
// executes between them to hide barrier latency + CTA skew.
// smem (floats): WtT 0, WaT 4096, WbT 8192, bs 12288(2x2048), cp 16384,
//                sg 18432, halo 20480(2x64), bt 20608, ba 20672, bb 20736
//                -> 20800 fl = 83200 B
// ===========================================================================
__global__ void __launch_bounds__(128, 1) __cluster_dims__(4, 1, 1)
col_scan_kernel(const float* __restrict__ Wc, const float* __restrict__ bc,
                const float* __restrict__ gms)
{
    float* sWtT = smdyn;
    float* sWaT = smdyn + 4096;
    float* sWbT = smdyn + 8192;
    float* bsB  = smdyn + 12288;
    float* cp   = smdyn + 16384;
    float* sg   = smdyn + 18432;
    float* halo = smdyn + 20480;
    float* sbt  = smdyn + 20608;
    float* sba  = smdyn + 20672;
    float* sbb  = smdyn + 20736;

    const int dir = blockIdx.z;     // 0 hse, 1 hsw, 2 hne, 3 hnw
    const int b   = blockIdx.y;
    const int cx  = blockIdx.x;     // cluster rank
    const int r0  = cx * 32;
    const int t   = threadIdx.x;

    int kt;
    if (dir == 0) kt = 2; else if (dir == 1) kt = 5; else if (dir == 2) kt = 10; else kt = 13;
    const int  wdir = (dir & 1) ? -1 : 1;
    const bool shup = (dir >= 2);
    const float gamma = gms[dir];

    for (int idx = t; idx < 4096; idx += 128) {
        int o = idx >> 6, c = idx & 63;
        sWtT[c * 64 + o] = Wc[kt * 4096 + idx];
        sWaT[c * 64 + o] = Wc[(kt + 1) * 4096 + idx];
        sWbT[c * 64 + o] = Wc[(kt + 2) * 4096 + idx];
    }
    if (t < 64) {
        sbt[t] = bc[kt * 64 + t];
        sba[t] = bc[(kt + 1) * 64 + t];
        sbb[t] = bc[(kt + 2) * 64 + t];
    }

    const float* baseb = ((dir < 2) ? g_hsT : g_hnT) + b * CHWX + r0;  // [c][w][h]
    const float* yTb   = g_yT + b * CHWX + r0;
    float*       outb  = g_col[dir] + b * CHWX + r0;

    // init column j0: 16 floats per thread
    {
        const int j0 = (wdir > 0) ? 0 : 127;
        const int c  = t >> 1;
        const int h0 = (t & 1) * 16;
        #pragma unroll
        for (int kk = 0; kk < 4; ++kk) {
            float4 v = relu4(*(const float4*)(baseb + c * HWX + j0 * 128 + h0 + kk * 4));
            *(float4*)(cp + c * 32 + h0 + kk * 4) = v;
            *(float4*)(outb + c * HWX + j0 * 128 + h0 + kk * 4) = v;
        }
    }
    // prefetch base column for step 1 into parity-1 buffer
    {
        const int j1 = (wdir > 0) ? 1 : 126;
        float* nb = bsB + 2048;
        #pragma unroll
        for (int k = 0; k < 4; ++k) {
            int q = t + 128 * k;
            int c = q >> 3, h = (q & 7) * 4;
            cpasync16(nb + c * 32 + h, baseb + c * HWX + j1 * 128 + h);
        }
        cpcommit();
    }

    const int o4 = (t >> 3) * 4;       // 4 out-channels
    const int hq = (t & 7) * 4;        // 4 local h rows

    for (int jj = 1; jj < 128; ++jj) {
        const int p = jj & 1;
        const float* bsP = bsB + p * 2048;
        const int j  = (wdir > 0) ? jj : 127 - jj;
        const int yj = j - wdir;

        cpwait0();
        __syncthreads();

        if (jj < 127) {
            const int j2 = (wdir > 0) ? jj + 1 : 126 - jj;
            float* nb = bsB + (1 - p) * 2048;
            #pragma unroll
            for (int k = 0; k < 4; ++k) {
                int q = t + 128 * k;
                int c = q >> 3, h = (q & 7) * 4;
                cpasync16(nb + c * 32 + h, baseb + c * HWX + j2 * 128 + h);
            }
            cpcommit();
        }

        float4 yv[4];
        #pragma unroll
        for (int k = 0; k < 4; ++k)
            yv[k] = *(const float4*)(yTb + (o4 + k) * HWX + yj * 128 + hq);

        ull aT[4][2], aA[4][2], aB[4][2];
        #pragma unroll
        for (int k = 0; k < 4; ++k) {
            aT[k][0] = aT[k][1] = 0ULL;
            aA[k][0] = aA[k][1] = 0ULL;
            aB[k][0] = aB[k][1] = 0ULL;
        }

        #pragma unroll 4
        for (int c = 0; c < 64; ++c) {
            double2 bv = *(const double2*)(bsP + c * 32 + hq);
            double2 pv = *(const double2*)(cp  + c * 32 + hq);
            ull b0 = dal(bv.x), b1 = dal(bv.y);
            ull p0 = dal(pv.x), p1 = dal(pv.y);
            float4 wt = *(const float4*)(sWtT + c * 64 + o4);
            float4 wa = *(const float4*)(sWaT + c * 64 + o4);
            float4 wb = *(const float4*)(sWbT + c * 64 + o4);
            float wt4[4] = {wt.x, wt.y, wt.z, wt.w};
            float wa4[4] = {wa.x, wa.y, wa.z, wa.w};
            float wb4[4] = {wb.x, wb.y, wb.z, wb.w};
            #pragma unroll
            for (int k = 0; k < 4; ++k) {
                ull w;
                w = dup2(wt4[k]); fma2(aT[k][0], p0, w); fma2(aT[k][1], p1, w);
                w = dup2(wa4[k]); fma2(aA[k][0], b0, w); fma2(aA[k][1], b1, w);
                w = dup2(wb4[k]); fma2(aB[k][0], p0, w); fma2(aB[k][1], p1, w);
            }
        }

        // gating (scalar epilogue) — sg must be in smem before arrive
        float g[4][4];
        #pragma unroll
        for (int k = 0; k < 4; ++k) {
            float2 t0 = unpk(aT[k][0]), t1 = unpk(aT[k][1]);
            const float bt_ = sbt[o4 + k];
            g[k][0] = (t0.x + bt_) * yv[k].x;
            g[k][1] = (t0.y + bt_) * yv[k].y;
            g[k][2] = (t1.x + bt_) * yv[k].z;
            g[k][3] = (t1.y + bt_) * yv[k].w;
            *(float4*)(sg + (o4 + k) * 32 + hq) =
                make_float4(g[k][0], g[k][1], g[k][2], g[k][3]);
        }

        // export boundary gated row to H-neighbor's halo (parity double-buffer)
        const int par = p * 64;
        if (!shup) {             // shift_down: my last local row -> cx+1
            if (hq == 28 && cx < 3) {
                #pragma unroll
                for (int k = 0; k < 4; ++k)
                    dsmem_store(halo + par + o4 + k, cx + 1, g[k][3]);
            }
        } else {                 // shift_up: my first local row -> cx-1
            if (hq == 0 && cx > 0) {
                #pragma unroll
                for (int k = 0; k < 4; ++k)
                    dsmem_store(halo + par + o4 + k, cx - 1, g[k][0]);
            }
        }

        // split barrier: arrive now, do halo-independent work, then wait
        asm volatile("barrier.cluster.arrive.aligned;" ::: "memory");

        // halo-independent epilogue: pre = A + ba + (B + bb) * y
        float pre[4][4];
        #pragma unroll
        for (int k = 0; k < 4; ++k) {
            float2 A0 = unpk(aA[k][0]), A1 = unpk(aA[k][1]);
            float2 B0 = unpk(aB[k][0]), B1 = unpk(aB[k][1]);
            const float ba_ = sba[o4 + k], bb_ = sbb[o4 + k];
            pre[k][0] = A0.x + ba_ + (B0.x + bb_) * yv[k].x;
            pre[k][1] = A0.y + ba_ + (B0.y + bb_) * yv[k].y;
            pre[k][2] = A1.x + ba_ + (B1.x + bb_) * yv[k].z;
            pre[k][3] = A1.y + ba_ + (B1.y + bb_) * yv[k].w;
        }

        asm volatile("barrier.cluster.wait.aligned;" ::: "memory");

        #pragma unroll
        for (int k = 0; k < 4; ++k) {
            const int o = o4 + k;
            float s0, s1, s2, s3;
            if (!shup) {         // shifted[h] = gated[h-1], 0 at global h=0
                float m;
                if (hq > 0)      m = sg[o * 32 + hq - 1];
                else if (cx > 0) m = halo[par + o];
                else             m = 0.f;
                s0 = m; s1 = g[k][0]; s2 = g[k][1]; s3 = g[k][2];
            } else {             // shifted[h] = gated[h+1], 0 at global h=127
                float q_;
                if (hq < 28)     q_ = sg[o * 32 + hq + 4];
                else if (cx < 3) q_ = halo[par + o];
                else             q_ = 0.f;
                s0 = g[k][1]; s1 = g[k][2]; s2 = g[k][3]; s3 = q_;
            }
            float4 cres;
            cres.x = fmaxf(pre[k][0] + gamma * s0, 0.f);
            cres.y = fmaxf(pre[k][1] + gamma * s1, 0.f);
            cres.z = fmaxf(pre[k][2] + gamma * s2, 0.f);
            cres.w = fmaxf(pre[k][3] + gamma * s3, 0.f);
            *(float4*)(cp + o * 32 + hq) = cres;
            *(float4*)(outb + o * HWX + j * 128 + hq) = cres;
        }
    }
}

// ===========================================================================
// Kernel 4: sum four direction buffers ([b][c][w][h]) and transpose to d_out.
// ===========================================================================
__global__ void __launch_bounds__(256, 1) sum_transpose_kernel(float* __restrict__ out)
{
    __shared__ float tile[32][33];
    const int n  = blockIdx.z;                 // b*64 + c
    const int w0 = blockIdx.y * 32, h0 = blockIdx.x * 32;
    const int tx = threadIdx.x & 31, ty = (threadIdx.x >> 5) * 4;
    const float* s0 = g_col[0] + n * HWX;
    const float* s1 = g_col[1] + n * HWX;
    const float* s2 = g_col[2] + n * HWX;
    const float* s3 = g_col[3] + n * HWX;
    #pragma unroll
    for (int k = 0; k < 4; ++k) {
        int idx = (w0 + ty + k) * 128 + h0 + tx;
        tile[ty + k][tx] = s0[idx] + s1[idx] + s2[idx] + s3[idx];
    }
    __syncthreads();
    float* d = out + n * HWX;
    #pragma unroll
    for (int k = 0; k < 4; ++k)
        d[(h0 + ty + k) * 128 + w0 + tx] = tile[tx][ty + k];
}

// ===========================================================================
extern "C" void kernel_launch(void* const* d_in, const int* in_sizes, int n_in,
                              void* d_out, int out_size)
{
    const float* x  = (const float*)d_in[0];
    const float* y  = (const float*)d_in[1];
    const float* Wc = (const float*)d_in[2];
    const float* bc = (const float*)d_in[3];
    const float* gm = (const float*)d_in[4];
    float* out = (float*)d_out;

    const int ROWSMEM = 13440 * 4;  // 53760 B
    const int COLSMEM = 20800 * 4;  // 83200 B
    cudaFuncSetAttribute(row_scan_kernel,
                         cudaFuncAttributeMaxDynamicSharedMemorySize, ROWSMEM);
    cudaFuncSetAttribute(col_scan_kernel,
                         cudaFuncAttributeMaxDynamicSharedMemorySize, COLSMEM);

    row_scan_kernel<<<dim3(8, 8, 2), 128, ROWSMEM>>>(x, y, Wc, bc);
    transpose3_kernel<<<dim3(4, 4, 1536), 256>>>(y);
    col_scan_kernel<<<dim3(4, 8, 4), 128, COLSMEM>>>(Wc, bc, gm);
    sum_transpose_kernel<<<dim3(4, 4, 512), 256>>>(out);

    (void)in_sizes; (void)n_in; (void)out_size;
}

// round 13
// speedup vs baseline: 1.4290x; 1.4290x over previous
#include <cuda_runtime.h>
#include <cstdint>

// Problem dims
#define HWX  16384      // 128*128
#define CHWX 1048576    // 64*128*128
#define TOTX 8388608    // 8*64*128*128

typedef unsigned long long ull;

// ---------------- device scratch (allocation-free rule: device globals) ----
__device__ __align__(16) float g_hs [TOTX];   // south row-scan, natural [b][c][h][w]
__device__ __align__(16) float g_hn [TOTX];   // north row-scan, natural
__device__ __align__(16) float g_hsT[TOTX];   // [b][c][w][h]
__device__ __align__(16) float g_hnT[TOTX];
__device__ __align__(16) float g_yT [TOTX];   // y transposed [b][c][w][h]
__device__ __align__(16) float g_col[4][TOTX];// per-direction col-scan output, [b][c][w][h]

// ---------------- f32x2 helpers -------------------------------------------
__device__ __forceinline__ ull dup2(float w) {
    ull r; asm("mov.b64 %0, {%1, %1};" : "=l"(r) : "f"(w)); return r;
}
__device__ __forceinline__ void fma2(ull& acc, ull a, ull b) {
    asm("fma.rn.f32x2 %0, %1, %2, %0;" : "+l"(acc) : "l"(a), "l"(b));
}
__device__ __forceinline__ float2 unpk(ull v) {
    float2 f; asm("mov.b64 {%0, %1}, %2;" : "=f"(f.x), "=f"(f.y) : "l"(v)); return f;
}
__device__ __forceinline__ ull dal(double d) { return __double_as_longlong(d); }

// ---------------- cp.async helpers ----------------------------------------
__device__ __forceinline__ void cpasync16(void* s, const void* g) {
    uint32_t sa = (uint32_t)__cvta_generic_to_shared(s);
    asm volatile("cp.async.ca.shared.global [%0], [%1], 16;" :: "r"(sa), "l"(g) : "memory");
}
__device__ __forceinline__ void cpcommit() { asm volatile("cp.async.commit_group;" ::: "memory"); }
__device__ __forceinline__ void cpwait0()  { asm volatile("cp.async.wait_group 0;"  ::: "memory"); }

// DSMEM scalar store into peer CTA's shared memory (cluster rank `rank`)
__device__ __forceinline__ void dsmem_store(float* laddr, int rank, float v) {
    uint32_t la = (uint32_t)__cvta_generic_to_shared(laddr);
    uint32_t ra;
    asm volatile("mapa.shared::cluster.u32 %0, %1, %2;" : "=r"(ra) : "r"(la), "r"(rank));
    asm volatile("st.shared::cluster.f32 [%0], %1;" :: "r"(ra), "f"(v) : "memory");
}

// ---------------- mbarrier helpers (p2p halo handshake) --------------------
__device__ __forceinline__ void mbar_init(uint32_t a, uint32_t cnt) {
    asm volatile("mbarrier.init.shared.b64 [%0], %1;" :: "r"(a), "r"(cnt) : "memory");
}
__device__ __forceinline__ void mbar_arrive_local(uint32_t a) {
    asm volatile("mbarrier.arrive.shared.b64 _, [%0];" :: "r"(a) : "memory");
}
// arrive on the same-offset barrier in cluster CTA `rank` (release, cluster scope)
__device__ __forceinline__ void mbar_arrive_remote(uint32_t a, int rank) {
    asm volatile(
        "{\n\t.reg .b32 ra;\n\t"
        "mapa.shared::cluster.u32 ra, %0, %1;\n\t"
        "mbarrier.arrive.release.cluster.shared::cluster.b64 _, [ra];\n\t}"
        :: "r"(a), "r"(rank) : "memory");
}
__device__ __forceinline__ void mbar_wait_acq(uint32_t a, uint32_t ph) {
    asm volatile(
        "{\n\t.reg .pred P;\n"
        "LW_%=:\n\t"
        "mbarrier.try_wait.parity.acquire.cluster.shared::cta.b64 P, [%0], %1, 0x989680;\n\t"
        "@P bra LD_%=;\n\t"
        "bra LW_%=;\n"
        "LD_%=:\n\t}"
        :: "r"(a), "r"(ph) : "memory");
}
__device__ __forceinline__ void mbar_wait_rlx(uint32_t a, uint32_t ph) {
    asm volatile(
        "{\n\t.reg .pred P;\n"
        "LW_%=:\n\t"
        "mbarrier.try_wait.parity.relaxed.cta.shared::cta.b64 P, [%0], %1, 0x989680;\n\t"
        "@P bra LD_%=;\n\t"
        "bra LW_%=;\n"
        "LD_%=:\n\t}"
        :: "r"(a), "r"(ph) : "memory");
}

__device__ __forceinline__ float4 relu4(float4 v) {
    v.x = fmaxf(v.x, 0.f); v.y = fmaxf(v.y, 0.f);
    v.z = fmaxf(v.z, 0.f); v.w = fmaxf(v.w, 0.f);
    return v;
}

extern __shared__ __align__(16) float smdyn[];

// ===========================================================================
// Kernel 1: row scans (south dir=0, north dir=1).  [identical to 713us build]
// ===========================================================================
__global__ void __launch_bounds__(128, 1) row_scan_kernel(
    const float* __restrict__ x, const float* __restrict__ y,
    const float* __restrict__ Wc, const float* __restrict__ bc)
{
    float* sWaT = smdyn;
    float* sWbT = smdyn + 4096;
    float* sx   = smdyn + 8192;
    float* sy   = smdyn + 10240;
    float* sh   = smdyn + 12288;
    float* sba  = smdyn + 13312;
    float* sbb  = smdyn + 13376;

    const int dir = blockIdx.z;          // 0 = south, 1 = north
    const int b   = blockIdx.y;
    const int w0  = blockIdx.x * 16;
    const int t   = threadIdx.x;

    const int ka = dir ? 8 : 0;
    const float* Wa = Wc + ka * 4096;
    const float* Wb = Wc + (ka + 1) * 4096;
    for (int idx = t; idx < 4096; idx += 128) {
        int o = idx >> 6, c = idx & 63;
        sWaT[c * 64 + o] = Wa[idx];
        sWbT[c * 64 + o] = Wb[idx];
    }
    if (t < 64) { sba[t] = bc[ka * 64 + t]; sbb[t] = bc[(ka + 1) * 64 + t]; }

    const float* xb = x + b * CHWX + w0;
    const float* yb = y + b * CHWX + w0;
    float* hb = (dir ? g_hn : g_hs) + b * CHWX + w0;

    {
        const int r0 = dir ? 127 : 0;
        const int c  = t >> 1;
        const int wv = (t & 1) * 8;
        #pragma unroll
        for (int kk = 0; kk < 2; ++kk) {
            float4 v = *(const float4*)(xb + c * HWX + r0 * 128 + wv + kk * 4);
            if (dir) v = relu4(v);
            *(float4*)(sh + c * 16 + wv + kk * 4) = v;
            *(float4*)(hb + c * HWX + r0 * 128 + wv + kk * 4) = v;
        }
    }
    {
        const int r2  = dir ? 126 : 1;
        const int yr2 = dir ? 127 : 0;
        #pragma unroll
        for (int k = 0; k < 2; ++k) {
            int q = t + 128 * k;
            int c = q >> 2, w = (q & 3) * 4;
            cpasync16(sx + 1024 + c * 16 + w, xb + c * HWX + r2  * 128 + w);
            cpasync16(sy + 1024 + c * 16 + w, yb + c * HWX + yr2 * 128 + w);
        }
        cpcommit();
    }

    const int o4 = (t >> 3) * 4;
    const int wq = (t & 7) * 2;

    for (int i = 1; i < 128; ++i) {
        const int p = i & 1;
        const float* sxP = sx + p * 1024;
        const float* syP = sy + p * 1024;
        const int r = dir ? 127 - i : i;

        cpwait0();
        __syncthreads();

        if (i < 127) {
            const int r2  = dir ? 127 - (i + 1) : (i + 1);
            const int yr2 = dir ? r2 + 1 : r2 - 1;
            float* sxN = sx + (1 - p) * 1024;
            float* syN = sy + (1 - p) * 1024;
            #pragma unroll
            for (int k = 0; k < 2; ++k) {
                int q = t + 128 * k;
                int c = q >> 2, w = (q & 3) * 4;
                cpasync16(sxN + c * 16 + w, xb + c * HWX + r2  * 128 + w);
                cpasync16(syN + c * 16 + w, yb + c * HWX + yr2 * 128 + w);
            }
            cpcommit();
        }

        ull aa[4], ab[4];
        #pragma unroll
        for (int k = 0; k < 4; ++k) { aa[k] = 0ULL; ab[k] = 0ULL; }

        #pragma unroll 4
        for (int c = 0; c < 64; ++c) {
            ull xv = dal(*(const double*)(sxP + c * 16 + wq));
            ull hv = dal(*(const double*)(sh  + c * 16 + wq));
            float4 wa = *(const float4*)(sWaT + c * 64 + o4);
            float4 wb = *(const float4*)(sWbT + c * 64 + o4);
            float wa4[4] = {wa.x, wa.y, wa.z, wa.w};
            float wb4[4] = {wb.x, wb.y, wb.z, wb.w};
            #pragma unroll
            for (int k = 0; k < 4; ++k) {
                fma2(aa[k], xv, dup2(wa4[k]));
                fma2(ab[k], hv, dup2(wb4[k]));
            }
        }

        float2 res[4];
        #pragma unroll
        for (int k = 0; k < 4; ++k) {
            const int o = o4 + k;
            float2 A  = unpk(aa[k]);
            float2 Bv = unpk(ab[k]);
            float2 yv = *(const float2*)(syP + o * 16 + wq);
            const float ba_ = sba[o], bb_ = sbb[o];
            res[k].x = fmaxf(A.x + ba_ + (Bv.x + bb_) * yv.x, 0.f);
            res[k].y = fmaxf(A.y + ba_ + (Bv.y + bb_) * yv.y, 0.f);
        }
        __syncthreads();
        #pragma unroll
        for (int k = 0; k < 4; ++k) {
            const int o = o4 + k;
            *(float2*)(sh + o * 16 + wq) = res[k];
            *(float2*)(hb + o * HWX + r * 128 + wq) = res[k];
        }
    }
}

// ===========================================================================
// Kernel 2: batched 128x128 transpose of last two dims.
// ===========================================================================
__global__ void __launch_bounds__(256, 1) transpose3_kernel(const float* __restrict__ ysrc)
{
    __shared__ float tile[32][33];
    const int mode = blockIdx.z >> 9;
    const int n    = blockIdx.z & 511;
    const float* src = (mode == 0 ? ysrc : (mode == 1 ? g_hs : g_hn)) + n * HWX;
    float*       dst = (mode == 0 ? g_yT : (mode == 1 ? g_hsT : g_hnT)) + n * HWX;
    const int r0 = blockIdx.y * 32, c0 = blockIdx.x * 32;
    const int tx = threadIdx.x & 31, ty = (threadIdx.x >> 5) * 4;
    #pragma unroll
    for (int k = 0; k < 4; ++k) tile[ty + k][tx] = src[(r0 + ty + k) * 128 + c0 + tx];
    __syncthreads();
    #pragma unroll
    for (int k = 0; k < 4; ++k) dst[(c0 + ty + k) * 128 + r0 + tx] = tile[tx][ty + k];
}

// ===========================================================================
// Kernel 3: column scans — R6 body, cluster barrier replaced by p2p mbarrier
// halo handshake (full/empty credits, parity-2) + local __syncthreads.
// smem (floats): WtT 0, WaT 4096, WbT 8192, bs 12288(2x2048), cp 16384,
//                sg 18432, halo 20480(2x64), bt 20608, ba 20672, bb 20736,
//                mbF 20800 (2 u64), mbE 20804 (2 u64) -> 20808 fl = 83232 B
// ===========================================================================
__global__ void __launch_bounds__(128, 1) __cluster_dims__(4, 1, 1)
col_scan_kernel(const float* __restrict__ Wc, const float* __restrict__ bc,
                const float* __restrict__ gms)
{
    float* sWtT = smdyn;
    float* sWaT = smdyn + 4096;
    float* sWbT = smdyn + 8192;
    float* bsB  = smdyn + 12288;
    float* cp   = smdyn + 16384;
    float* sg   = smdyn + 18432;
    float* halo = smdyn + 20480;
    float* sbt  = smdyn + 20608;
    float* sba  = smdyn + 20672;
    float* sbb  = smdyn + 20736;
    const uint32_t smbase = (uint32_t)__cvta_generic_to_shared(smdyn);
    const uint32_t mbF0 = smbase + 20800 * 4;   // full[0], full[1]
    const uint32_t mbE0 = smbase + 20804 * 4;   // empty[0], empty[1]

    const int dir = blockIdx.z;     // 0 hse, 1 hsw, 2 hne, 3 hnw
    const int b   = blockIdx.y;
    const int cx  = blockIdx.x;     // cluster rank
    const int r0  = cx * 32;
    const int t   = threadIdx.x;

    int kt;
    if (dir == 0) kt = 2; else if (dir == 1) kt = 5; else if (dir == 2) kt = 10; else kt = 13;
    const int  wdir = (dir & 1) ? -1 : 1;
    const bool shup = (dir >= 2);
    const float gamma = gms[dir];

    for (int idx = t; idx < 4096; idx += 128) {
        int o = idx >> 6, c = idx & 63;
        sWtT[c * 64 + o] = Wc[kt * 4096 + idx];
        sWaT[c * 64 + o] = Wc[(kt + 1) * 4096 + idx];
        sWbT[c * 64 + o] = Wc[(kt + 2) * 4096 + idx];
    }
    if (t < 64) {
        sbt[t] = bc[kt * 64 + t];
        sba[t] = bc[(kt + 1) * 64 + t];
        sbb[t] = bc[(kt + 2) * 64 + t];
    }
    // mbarrier init: full count = 16 (one release-arrive per exporter thread),
    // empty count = 1 (elected consumer credit). Prime empties so the first
    // use of each slot (phase 0) passes immediately.
    if (t == 0) {
        mbar_init(mbF0,     16); mbar_init(mbF0 + 8, 16);
        mbar_init(mbE0,      1); mbar_init(mbE0 + 8,  1);
        mbar_arrive_local(mbE0); mbar_arrive_local(mbE0 + 8);
    }
    __syncthreads();
    // cluster-wide: all CTAs' barriers initialized before any remote op
    asm volatile("barrier.cluster.arrive.aligned;" ::: "memory");
    asm volatile("barrier.cluster.wait.aligned;"   ::: "memory");

    const float* baseb = ((dir < 2) ? g_hsT : g_hnT) + b * CHWX + r0;  // [c][w][h]
    const float* yTb   = g_yT + b * CHWX + r0;
    float*       outb  = g_col[dir] + b * CHWX + r0;

    // init column j0: 16 floats per thread
    {
        const int j0 = (wdir > 0) ? 0 : 127;
        const int c  = t >> 1;
        const int h0 = (t & 1) * 16;
        #pragma unroll
        for (int kk = 0; kk < 4; ++kk) {
            float4 v = relu4(*(const float4*)(baseb + c * HWX + j0 * 128 + h0 + kk * 4));
            *(float4*)(cp + c * 32 + h0 + kk * 4) = v;
            *(float4*)(outb + c * HWX + j0 * 128 + h0 + kk * 4) = v;
        }
    }
    // prefetch base column for step 1 into parity-1 buffer
    {
        const int j1 = (wdir > 0) ? 1 : 126;
        float* nb = bsB + 2048;
        #pragma unroll
        for (int k = 0; k < 4; ++k) {
            int q = t + 128 * k;
            int c = q >> 3, h = (q & 7) * 4;
            cpasync16(nb + c * 32 + h, baseb + c * HWX + j1 * 128 + h);
        }
        cpcommit();
    }

    const int o4 = (t >> 3) * 4;       // 4 out-channels
    const int hq = (t & 7) * 4;        // 4 local h rows

    // halo roles
    const bool is_exp  = shup ? (hq == 0)  : (hq == 28);  // exports boundary row
    const bool is_rdr  = shup ? (hq == 28) : (hq == 0);   // reads halo
    const bool has_out = shup ? (cx > 0)   : (cx < 3);    // neighbor I send to
    const bool has_in  = shup ? (cx < 3)   : (cx > 0);    // neighbor I receive from
    const int  rank_out = shup ? cx - 1 : cx + 1;
    const int  rank_in  = shup ? cx + 1 : cx - 1;
    int phF0 = 0, phF1 = 0;   // consumer phases for full[0/1]
    int phE0 = 0, phE1 = 0;   // producer phases for empty[0/1] (primed)

    for (int jj = 1; jj < 128; ++jj) {
        const int p = jj & 1;
        const float* bsP = bsB + p * 2048;
        const int j  = (wdir > 0) ? jj : 127 - jj;
        const int yj = j - wdir;

        cpwait0();
        __syncthreads();

        // return the credit for the slot consumed last step (all reads done,
        // guaranteed by the syncthreads above)
        if (t == 0 && has_in && jj >= 2)
            mbar_arrive_remote(mbE0 + (1 - p) * 8, rank_in);

        if (jj < 127) {
            const int j2 = (wdir > 0) ? jj + 1 : 126 - jj;
            float* nb = bsB + (1 - p) * 2048;
            #pragma unroll
            for (int k = 0; k < 4; ++k) {
                int q = t + 128 * k;
                int c = q >> 3, h = (q & 7) * 4;
                cpasync16(nb + c * 32 + h, baseb + c * HWX + j2 * 128 + h);
            }
            cpcommit();
        }

        float4 yv[4];
        #pragma unroll
        for (int k = 0; k < 4; ++k)
            yv[k] = *(const float4*)(yTb + (o4 + k) * HWX + yj * 128 + hq);

        ull aT[4][2], aA[4][2], aB[4][2];
        #pragma unroll
        for (int k = 0; k < 4; ++k) {
            aT[k][0] = aT[k][1] = 0ULL;
            aA[k][0] = aA[k][1] = 0ULL;
            aB[k][0] = aB[k][1] = 0ULL;
        }

        #pragma unroll 4
        for (int c = 0; c < 64; ++c) {
            double2 bv = *(const double2*)(bsP + c * 32 + hq);
            double2 pv = *(const double2*)(cp  + c * 32 + hq);
            ull b0 = dal(bv.x), b1 = dal(bv.y);
            ull p0 = dal(pv.x), p1 = dal(pv.y);
            float4 wt = *(const float4*)(sWtT + c * 64 + o4);
            float4 wa = *(const float4*)(sWaT + c * 64 + o4);
            float4 wb = *(const float4*)(sWbT + c * 64 + o4);
            float wt4[4] = {wt.x, wt.y, wt.z, wt.w};
            float wa4[4] = {wa.x, wa.y, wa.z, wa.w};
            float wb4[4] = {wb.x, wb.y, wb.z, wb.w};
            #pragma unroll
            for (int k = 0; k < 4; ++k) {
                ull w;
                w = dup2(wt4[k]); fma2(aT[k][0], p0, w); fma2(aT[k][1], p1, w);
                w = dup2(wa4[k]); fma2(aA[k][0], b0, w); fma2(aA[k][1], b1, w);
                w = dup2(wb4[k]); fma2(aB[k][0], p0, w); fma2(aB[k][1], p1, w);
            }
        }

        // gating (scalar epilogue); sg stores ordered vs readers by the
        // __syncthreads below
        float g[4][4];
        #pragma unroll
        for (int k = 0; k < 4; ++k) {
            float2 t0 = unpk(aT[k][0]), t1 = unpk(aT[k][1]);
            const float bt_ = sbt[o4 + k];
            g[k][0] = (t0.x + bt_) * yv[k].x;
            g[k][1] = (t0.y + bt_) * yv[k].y;
            g[k][2] = (t1.x + bt_) * yv[k].z;
            g[k][3] = (t1.y + bt_) * yv[k].w;
            *(float4*)(sg + (o4 + k) * 32 + hq) =
                make_float4(g[k][0], g[k][1], g[k][2], g[k][3]);
        }

        // producer: wait slot credit, export boundary row, signal full
        const int par = p * 64;
        if (is_exp && has_out) {
            int& phE = p ? phE1 : phE0;
            mbar_wait_rlx(mbE0 + p * 8, phE); phE ^= 1;
            #pragma unroll
            for (int k = 0; k < 4; ++k)
                dsmem_store(halo + par + o4 + k, rank_out,
                            shup ? g[k][0] : g[k][3]);
            mbar_arrive_remote(mbF0 + p * 8, rank_out);
        }

        __syncthreads();   // local: sg visible to all readers

        // consumer: wait for neighbor's halo row
        if (is_rdr && has_in) {
            int& phF = p ? phF1 : phF0;
            mbar_wait_acq(mbF0 + p * 8, phF); phF ^= 1;
        }

        #pragma unroll
        for (int k = 0; k < 4; ++k) {
            const int o = o4 + k;
            float s0, s1, s2, s3;
            if (!shup) {         // shifted[h] = gated[h-1], 0 at global h=0
                float m;
                if (hq > 0)      m = sg[o * 32 + hq - 1];
                else if (cx > 0) m = halo[par + o];
                else             m = 0.f;
                s0 = m; s1 = g[k][0]; s2 = g[k][1]; s3 = g[k][2];
            } else {             // shifted[h] = gated[h+1], 0 at global h=127
                float q_;
                if (hq < 28)     q_ = sg[o * 32 + hq + 4];
                else if (cx < 3) q_ = halo[par + o];
                else             q_ = 0.f;
                s0 = g[k][1]; s1 = g[k][2]; s2 = g[k][3]; s3 = q_;
            }
            float2 A0 = unpk(aA[k][0]), A1 = unpk(aA[k][1]);
            float2 B0 = unpk(aB[k][0]), B1 = unpk(aB[k][1]);
            const float ba_ = sba[o], bb_ = sbb[o];
            float4 cres;
            cres.x = fmaxf(A0.x + ba_ + (B0.x + bb_) * yv[k].x + gamma * s0, 0.f);
            cres.y = fmaxf(A0.y + ba_ + (B0.y + bb_) * yv[k].y + gamma * s1, 0.f);
            cres.z = fmaxf(A1.x + ba_ + (B1.x + bb_) * yv[k].z + gamma * s2, 0.f);
            cres.w = fmaxf(A1.y + ba_ + (B1.y + bb_) * yv[k].w + gamma * s3, 0.f);
            *(float4*)(cp + o * 32 + hq) = cres;
            *(float4*)(outb + o * HWX + j * 128 + hq) = cres;
        }
    }

    // keep cluster smem alive until all CTAs' in-flight remote ops complete
    asm volatile("barrier.cluster.arrive.aligned;" ::: "memory");
    asm volatile("barrier.cluster.wait.aligned;"   ::: "memory");
}

// ===========================================================================
// Kernel 4: sum four direction buffers ([b][c][w][h]) and transpose to d_out.
// ===========================================================================
__global__ void __launch_bounds__(256, 1) sum_transpose_kernel(float* __restrict__ out)
{
    __shared__ float tile[32][33];
    const int n  = blockIdx.z;                 // b*64 + c
    const int w0 = blockIdx.y * 32, h0 = blockIdx.x * 32;
    const int tx = threadIdx.x & 31, ty = (threadIdx.x >> 5) * 4;
    const float* s0 = g_col[0] + n * HWX;
    const float* s1 = g_col[1] + n * HWX;
    const float* s2 = g_col[2] + n * HWX;
    const float* s3 = g_col[3] + n * HWX;
    #pragma unroll
    for (int k = 0; k < 4; ++k) {
        int idx = (w0 + ty + k) * 128 + h0 + tx;
        tile[ty + k][tx] = s0[idx] + s1[idx] + s2[idx] + s3[idx];
    }
    __syncthreads();
    float* d = out + n * HWX;
    #pragma unroll
    for (int k = 0; k < 4; ++k)
        d[(h0 + ty + k) * 128 + w0 + tx] = tile[tx][ty + k];
}

// ===========================================================================
extern "C" void kernel_launch(void* const* d_in, const int* in_sizes, int n_in,
                              void* d_out, int out_size)
{
    const float* x  = (const float*)d_in[0];
    const float* y  = (const float*)d_in[1];
    const float* Wc = (const float*)d_in[2];
    const float* bc = (const float*)d_in[3];
    const float* gm = (const float*)d_in[4];
    float* out = (float*)d_out;

    const int ROWSMEM = 13440 * 4;  // 53760 B
    const int COLSMEM = 20808 * 4;  // 83232 B
    cudaFuncSetAttribute(row_scan_kernel,
                         cudaFuncAttributeMaxDynamicSharedMemorySize, ROWSMEM);
    cudaFuncSetAttribute(col_scan_kernel,
                         cudaFuncAttributeMaxDynamicSharedMemorySize, COLSMEM);

    row_scan_kernel<<<dim3(8, 8, 2), 128, ROWSMEM>>>(x, y, Wc, bc);
    transpose3_kernel<<<dim3(4, 4, 1536), 256>>>(y);
    col_scan_kernel<<<dim3(4, 8, 4), 128, COLSMEM>>>(Wc, bc, gm);
    sum_transpose_kernel<<<dim3(4, 4, 512), 256>>>(out);

    (void)in_sizes; (void)n_in; (void)out_size;
}

// round 17
// speedup vs baseline: 1.4787x; 1.0348x over previous
#include <cuda_runtime.h>
#include <cstdint>

// Problem dims
#define HWX  16384      // 128*128
#define CHWX 1048576    // 64*128*128
#define TOTX 8388608    // 8*64*128*128

typedef unsigned long long ull;

// ---------------- device scratch (allocation-free rule: device globals) ----
__device__ __align__(16) float g_hs [TOTX];   // south row-scan, natural [b][c][h][w]
__device__ __align__(16) float g_hn [TOTX];   // north row-scan, natural
__device__ __align__(16) float g_hsT[TOTX];   // [b][c][w][h]
__device__ __align__(16) float g_hnT[TOTX];
__device__ __align__(16) float g_yT [TOTX];   // y transposed [b][c][w][h]
__device__ __align__(16) float g_col[4][TOTX];// per-direction col-scan output, [b][c][w][h]

// ---------------- f32x2 helpers -------------------------------------------
__device__ __forceinline__ ull dup2(float w) {
    ull r; asm("mov.b64 %0, {%1, %1};" : "=l"(r) : "f"(w)); return r;
}
__device__ __forceinline__ void fma2(ull& acc, ull a, ull b) {
    asm("fma.rn.f32x2 %0, %1, %2, %0;" : "+l"(acc) : "l"(a), "l"(b));
}
__device__ __forceinline__ float2 unpk(ull v) {
    float2 f; asm("mov.b64 {%0, %1}, %2;" : "=f"(f.x), "=f"(f.y) : "l"(v)); return f;
}
__device__ __forceinline__ ull dal(double d) { return __double_as_longlong(d); }

// ---------------- cp.async helpers ----------------------------------------
__device__ __forceinline__ void cpasync16(void* s, const void* g) {
    uint32_t sa = (uint32_t)__cvta_generic_to_shared(s);
    asm volatile("cp.async.ca.shared.global [%0], [%1], 16;" :: "r"(sa), "l"(g) : "memory");
}
__device__ __forceinline__ void cpcommit() { asm volatile("cp.async.commit_group;" ::: "memory"); }
__device__ __forceinline__ void cpwait0()  { asm volatile("cp.async.wait_group 0;"  ::: "memory"); }

// DSMEM scalar store into peer CTA's shared memory (cluster rank `rank`)
__device__ __forceinline__ void dsmem_store(float* laddr, int rank, float v) {
    uint32_t la = (uint32_t)__cvta_generic_to_shared(laddr);
    uint32_t ra;
    asm volatile("mapa.shared::cluster.u32 %0, %1, %2;" : "=r"(ra) : "r"(la), "r"(rank));
    asm volatile("st.shared::cluster.f32 [%0], %1;" :: "r"(ra), "f"(v) : "memory");
}

__device__ __forceinline__ float4 relu4(float4 v) {
    v.x = fmaxf(v.x, 0.f); v.y = fmaxf(v.y, 0.f);
    v.z = fmaxf(v.z, 0.f); v.w = fmaxf(v.w, 0.f);
    return v;
}

extern __shared__ __align__(16) float smdyn[];

// ===========================================================================
// Kernel 1: row scans (south dir=0, north dir=1).  [exact 713us build]
// grid (8 w-tiles, 8 batch, 2 dirs), 128 threads.
// Thread tile: 4 o x 2 w (one f32x2 pair). Weights [c][o] + dup2.
// smem (floats): WaT 0, WbT 4096, sx 8192(2x1024), sy 10240(2x1024),
//                sh 12288, ba 13312, bb 13376  -> 13440 fl = 53760 B
// ===========================================================================
__global__ void __launch_bounds__(128, 1) row_scan_kernel(
    const float* __restrict__ x, const float* __restrict__ y,
    const float* __restrict__ Wc, const float* __restrict__ bc)
{
    float* sWaT = smdyn;
    float* sWbT = smdyn + 4096;
    float* sx   = smdyn + 8192;
    float* sy   = smdyn + 10240;
    float* sh   = smdyn + 12288;
    float* sba  = smdyn + 13312;
    float* sbb  = smdyn + 13376;

    const int dir = blockIdx.z;          // 0 = south, 1 = north
    const int b   = blockIdx.y;
    const int w0  = blockIdx.x * 16;
    const int t   = threadIdx.x;

    const int ka = dir ? 8 : 0;
    const float* Wa = Wc + ka * 4096;
    const float* Wb = Wc + (ka + 1) * 4096;
    for (int idx = t; idx < 4096; idx += 128) {
        int o = idx >> 6, c = idx & 63;
        sWaT[c * 64 + o] = Wa[idx];
        sWbT[c * 64 + o] = Wb[idx];
    }
    if (t < 64) { sba[t] = bc[ka * 64 + t]; sbb[t] = bc[(ka + 1) * 64 + t]; }

    const float* xb = x + b * CHWX + w0;
    const float* yb = y + b * CHWX + w0;
    float* hb = (dir ? g_hn : g_hs) + b * CHWX + w0;

    {
        const int r0 = dir ? 127 : 0;
        const int c  = t >> 1;
        const int wv = (t & 1) * 8;
        #pragma unroll
        for (int kk = 0; kk < 2; ++kk) {
            float4 v = *(const float4*)(xb + c * HWX + r0 * 128 + wv + kk * 4);
            if (dir) v = relu4(v);
            *(float4*)(sh + c * 16 + wv + kk * 4) = v;
            *(float4*)(hb + c * HWX + r0 * 128 + wv + kk * 4) = v;
        }
    }
    {
        const int r2  = dir ? 126 : 1;
        const int yr2 = dir ? 127 : 0;
        #pragma unroll
        for (int k = 0; k < 2; ++k) {
            int q = t + 128 * k;
            int c = q >> 2, w = (q & 3) * 4;
            cpasync16(sx + 1024 + c * 16 + w, xb + c * HWX + r2  * 128 + w);
            cpasync16(sy + 1024 + c * 16 + w, yb + c * HWX + yr2 * 128 + w);
        }
        cpcommit();
    }

    const int o4 = (t >> 3) * 4;
    const int wq = (t & 7) * 2;

    for (int i = 1; i < 128; ++i) {
        const int p = i & 1;
        const float* sxP = sx + p * 1024;
        const float* syP = sy + p * 1024;
        const int r = dir ? 127 - i : i;

        cpwait0();
        __syncthreads();

        if (i < 127) {
            const int r2  = dir ? 127 - (i + 1) : (i + 1);
            const int yr2 = dir ? r2 + 1 : r2 - 1;
            float* sxN = sx + (1 - p) * 1024;
            float* syN = sy + (1 - p) * 1024;
            #pragma unroll
            for (int k = 0; k < 2; ++k) {
                int q = t + 128 * k;
                int c = q >> 2, w = (q & 3) * 4;
                cpasync16(sxN + c * 16 + w, xb + c * HWX + r2  * 128 + w);
                cpasync16(syN + c * 16 + w, yb + c * HWX + yr2 * 128 + w);
            }
            cpcommit();
        }

        ull aa[4], ab[4];
        #pragma unroll
        for (int k = 0; k < 4; ++k) { aa[k] = 0ULL; ab[k] = 0ULL; }

        #pragma unroll 8
        for (int c = 0; c < 64; ++c) {
            ull xv = dal(*(const double*)(sxP + c * 16 + wq));
            ull hv = dal(*(const double*)(sh  + c * 16 + wq));
            float4 wa = *(const float4*)(sWaT + c * 64 + o4);
            float4 wb = *(const float4*)(sWbT + c * 64 + o4);
            float wa4[4] = {wa.x, wa.y, wa.z, wa.w};
            float wb4[4] = {wb.x, wb.y, wb.z, wb.w};
            #pragma unroll
            for (int k = 0; k < 4; ++k) {
                fma2(aa[k], xv, dup2(wa4[k]));
                fma2(ab[k], hv, dup2(wb4[k]));
            }
        }

        float2 res[4];
        #pragma unroll
        for (int k = 0; k < 4; ++k) {
            const int o = o4 + k;
            float2 A  = unpk(aa[k]);
            float2 Bv = unpk(ab[k]);
            float2 yv = *(const float2*)(syP + o * 16 + wq);
            const float ba_ = sba[o], bb_ = sbb[o];
            res[k].x = fmaxf(A.x + ba_ + (Bv.x + bb_) * yv.x, 0.f);
            res[k].y = fmaxf(A.y + ba_ + (Bv.y + bb_) * yv.y, 0.f);
        }
        __syncthreads();
        #pragma unroll
        for (int k = 0; k < 4; ++k) {
            const int o = o4 + k;
            *(float2*)(sh + o * 16 + wq) = res[k];
            *(float2*)(hb + o * HWX + r * 128 + wq) = res[k];
        }
    }
}

// ===========================================================================
// Kernel 2: batched 128x128 transpose of last two dims.
// ===========================================================================
__global__ void __launch_bounds__(256, 1) transpose3_kernel(const float* __restrict__ ysrc)
{
    __shared__ float tile[32][33];
    const int mode = blockIdx.z >> 9;
    const int n    = blockIdx.z & 511;
    const float* src = (mode == 0 ? ysrc : (mode == 1 ? g_hs : g_hn)) + n * HWX;
    float*       dst = (mode == 0 ? g_yT : (mode == 1 ? g_hsT : g_hnT)) + n * HWX;
    const int r0 = blockIdx.y * 32, c0 = blockIdx.x * 32;
    const int tx = threadIdx.x & 31, ty = (threadIdx.x >> 5) * 4;
    #pragma unroll
    for (int k = 0; k < 4; ++k) tile[ty + k][tx] = src[(r0 + ty + k) * 128 + c0 + tx];
    __syncthreads();
    #pragma unroll
    for (int k = 0; k < 4; ++k) dst[(c0 + ty + k) * 128 + r0 + tx] = tile[tx][ty + k];
}

// ===========================================================================
// Kernel 3: column scans, all 4 directions in one launch.
// grid (4 H-chunks [cluster 4], 8 batch, 4 dirs), 256 threads (2 warps/SMSP).
// Thread tile: 4 o x 2 h; f32x2 lanes = adjacent OUT-CHANNEL pairs so weight
// LDS.128 feeds FFMA2 directly (no weight MOVs); only 4 data dups per c-iter.
// Sync protocol identical to the 713us build (per-step cluster barrier).
// smem (floats): WtT 0, WaT 4096, WbT 8192, bs 12288(2x2048), cp 16384,
//                sg 18432, halo 20480(2x64), bt 20608, ba 20672, bb 20736
//                -> 20800 fl = 83200 B
// ===========================================================================
__global__ void __launch_bounds__(256, 1) __cluster_dims__(4, 1, 1)
col_scan_kernel(const float* __restrict__ Wc, const float* __restrict__ bc,
                const float* __restrict__ gms)
{
    float* sWtT = smdyn;
    float* sWaT = smdyn + 4096;
    float* sWbT = smdyn + 8192;
    float* bsB  = smdyn + 12288;
    float* cp   = smdyn + 16384;
    float* sg   = smdyn + 18432;
    float* halo = smdyn + 20480;
    float* sbt  = smdyn + 20608;
    float* sba  = smdyn + 20672;
    float* sbb  = smdyn + 20736;

    const int dir = blockIdx.z;     // 0 hse, 1 hsw, 2 hne, 3 hnw
    const int b   = blockIdx.y;
    const int cx  = blockIdx.x;     // cluster rank
    const int r0  = cx * 32;
    const int t   = threadIdx.x;

    int kt;
    if (dir == 0) kt = 2; else if (dir == 1) kt = 5; else if (dir == 2) kt = 10; else kt = 13;
    const int  wdir = (dir & 1) ? -1 : 1;
    const bool shup = (dir >= 2);
    const float gamma = gms[dir];

    for (int idx = t; idx < 4096; idx += 256) {
        int o = idx >> 6, c = idx & 63;
        sWtT[c * 64 + o] = Wc[kt * 4096 + idx];
        sWaT[c * 64 + o] = Wc[(kt + 1) * 4096 + idx];
        sWbT[c * 64 + o] = Wc[(kt + 2) * 4096 + idx];
    }
    if (t < 64) {
        sbt[t] = bc[kt * 64 + t];
        sba[t] = bc[(kt + 1) * 64 + t];
        sbb[t] = bc[(kt + 2) * 64 + t];
    }

    const float* baseb = ((dir < 2) ? g_hsT : g_hnT) + b * CHWX + r0;  // [c][w][h]
    const float* yTb   = g_yT + b * CHWX + r0;
    float*       outb  = g_col[dir] + b * CHWX + r0;

    // init column j0: 8 floats per thread
    {
        const int j0 = (wdir > 0) ? 0 : 127;
        const int c  = t >> 2;
        const int h0 = (t & 3) * 8;
        #pragma unroll
        for (int kk = 0; kk < 2; ++kk) {
            float4 v = relu4(*(const float4*)(baseb + c * HWX + j0 * 128 + h0 + kk * 4));
            *(float4*)(cp + c * 32 + h0 + kk * 4) = v;
            *(float4*)(outb + c * HWX + j0 * 128 + h0 + kk * 4) = v;
        }
    }
    // prefetch base column for step 1 into parity-1 buffer (512 cp16, 2/thread)
    {
        const int j1 = (wdir > 0) ? 1 : 126;
        float* nb = bsB + 2048;
        #pragma unroll
        for (int k = 0; k < 2; ++k) {
            int q = t + 256 * k;
            int c = q >> 3, h = (q & 7) * 4;
            cpasync16(nb + c * 32 + h, baseb + c * HWX + j1 * 128 + h);
        }
        cpcommit();
    }

    const int o4 = (t >> 4) * 4;       // 4 out-channels (2 lane-pairs)
    const int h2 = (t & 15) * 2;       // 2 local h rows

    for (int jj = 1; jj < 128; ++jj) {
        const int p = jj & 1;
        const float* bsP = bsB + p * 2048;
        const int j  = (wdir > 0) ? jj : 127 - jj;
        const int yj = j - wdir;

        cpwait0();
        __syncthreads();

        if (jj < 127) {
            const int j2 = (wdir > 0) ? jj + 1 : 126 - jj;
            float* nb = bsB + (1 - p) * 2048;
            #pragma unroll
            for (int k = 0; k < 2; ++k) {
                int q = t + 256 * k;
                int c = q >> 3, h = (q & 7) * 4;
                cpasync16(nb + c * 32 + h, baseb + c * HWX + j2 * 128 + h);
            }
            cpcommit();
        }

        float2 y2[4];
        #pragma unroll
        for (int k = 0; k < 4; ++k)
            y2[k] = *(const float2*)(yTb + (o4 + k) * HWX + yj * 128 + h2);

        // accumulators: [o-pair][h]; lanes hold (o4+2p, o4+2p+1)
        ull aT[2][2], aA[2][2], aB[2][2];
        #pragma unroll
        for (int q = 0; q < 2; ++q) {
            aT[q][0] = aT[q][1] = 0ULL;
            aA[q][0] = aA[q][1] = 0ULL;
            aB[q][0] = aB[q][1] = 0ULL;
        }

        #pragma unroll 8
        for (int c = 0; c < 64; ++c) {
            float2 bv = *(const float2*)(bsP + c * 32 + h2);
            float2 pv = *(const float2*)(cp  + c * 32 + h2);
            ull b0 = dup2(bv.x), b1 = dup2(bv.y);
            ull p0 = dup2(pv.x), p1 = dup2(pv.y);
            double2 wtq = *(const double2*)(sWtT + c * 64 + o4);
            double2 waq = *(const double2*)(sWaT + c * 64 + o4);
            double2 wbq = *(const double2*)(sWbT + c * 64 + o4);
            ull wt0 = dal(wtq.x), wt1 = dal(wtq.y);
            ull wa0 = dal(waq.x), wa1 = dal(waq.y);
            ull wb0 = dal(wbq.x), wb1 = dal(wbq.y);
            fma2(aT[0][0], p0, wt0); fma2(aT[0][1], p1, wt0);
            fma2(aT[1][0], p0, wt1); fma2(aT[1][1], p1, wt1);
            fma2(aA[0][0], b0, wa0); fma2(aA[0][1], b1, wa0);
            fma2(aA[1][0], b0, wa1); fma2(aA[1][1], b1, wa1);
            fma2(aB[0][0], p0, wb0); fma2(aB[0][1], p1, wb0);
            fma2(aB[1][0], p0, wb1); fma2(aB[1][1], p1, wb1);
        }

        // gating: g[k][h] for this thread's 4 o x 2 h
        float g[4][2];
        #pragma unroll
        for (int q = 0; q < 2; ++q) {
            float2 t0 = unpk(aT[q][0]);   // h2   : lanes (o4+2q, o4+2q+1)
            float2 t1 = unpk(aT[q][1]);   // h2+1
            const int k0 = 2 * q, k1 = 2 * q + 1;
            const float bt0 = sbt[o4 + k0], bt1 = sbt[o4 + k1];
            g[k0][0] = (t0.x + bt0) * y2[k0].x;
            g[k1][0] = (t0.y + bt1) * y2[k1].x;
            g[k0][1] = (t1.x + bt0) * y2[k0].y;
            g[k1][1] = (t1.y + bt1) * y2[k1].y;
        }
        #pragma unroll
        for (int k = 0; k < 4; ++k)
            *(float2*)(sg + (o4 + k) * 32 + h2) = make_float2(g[k][0], g[k][1]);

        // export boundary gated row to H-neighbor's halo (parity double-buffer)
        const int par = p * 64;
        if (!shup) {             // shift_down: my last local row (h=31) -> cx+1
            if (h2 == 30 && cx < 3) {
                #pragma unroll
                for (int k = 0; k < 4; ++k)
                    dsmem_store(halo + par + o4 + k, cx + 1, g[k][1]);
            }
        } else {                 // shift_up: my first local row (h=0) -> cx-1
            if (h2 == 0 && cx > 0) {
                #pragma unroll
                for (int k = 0; k < 4; ++k)
                    dsmem_store(halo + par + o4 + k, cx - 1, g[k][0]);
            }
        }
        asm volatile("barrier.cluster.arrive.aligned;" ::: "memory");
        asm volatile("barrier.cluster.wait.aligned;"   ::: "memory");

        #pragma unroll
        for (int q = 0; q < 2; ++q) {
            float2 A0 = unpk(aA[q][0]), A1 = unpk(aA[q][1]);
            float2 B0 = unpk(aB[q][0]), B1 = unpk(aB[q][1]);
            const int kk[2] = { 2 * q, 2 * q + 1 };
            const float Ah[2][2] = { {A0.x, A1.x}, {A0.y, A1.y} };  // [k in pair][h]
            const float Bh[2][2] = { {B0.x, B1.x}, {B0.y, B1.y} };
            #pragma unroll
            for (int m = 0; m < 2; ++m) {
                const int k = kk[m];
                const int o = o4 + k;
                float s0, s1;
                if (!shup) {     // shifted[h] = gated[h-1], 0 at global h=0
                    float mm;
                    if (h2 > 0)      mm = sg[o * 32 + h2 - 1];
                    else if (cx > 0) mm = halo[par + o];
                    else             mm = 0.f;
                    s0 = mm; s1 = g[k][0];
                } else {         // shifted[h] = gated[h+1], 0 at global h=127
                    float qq;
                    if (h2 < 30)     qq = sg[o * 32 + h2 + 2];
                    else if (cx < 3) qq = halo[par + o];
                    else             qq = 0.f;
                    s0 = g[k][1]; s1 = qq;
                }
                const float ba_ = sba[o], bb_ = sbb[o];
                float2 cres;
                cres.x = fmaxf(Ah[m][0] + ba_ + (Bh[m][0] + bb_) * y2[k].x + gamma * s0, 0.f);
                cres.y = fmaxf(Ah[m][1] + ba_ + (Bh[m][1] + bb_) * y2[k].y + gamma * s1, 0.f);
                *(float2*)(cp + o * 32 + h2) = cres;
                *(float2*)(outb + o * HWX + j * 128 + h2) = cres;
            }
        }
    }
}

// ===========================================================================
// Kernel 4: sum four direction buffers ([b][c][w][h]) and transpose to d_out.
// ===========================================================================
__global__ void __launch_bounds__(256, 1) sum_transpose_kernel(float* __restrict__ out)
{
    __shared__ float tile[32][33];
    const int n  = blockIdx.z;                 // b*64 + c
    const int w0 = blockIdx.y * 32, h0 = blockIdx.x * 32;
    const int tx = threadIdx.x & 31, ty = (threadIdx.x >> 5) * 4;
    const float* s0 = g_col[0] + n * HWX;
    const float* s1 = g_col[1] + n * HWX;
    const float* s2 = g_col[2] + n * HWX;
    const float* s3 = g_col[3] + n * HWX;
    #pragma unroll
    for (int k = 0; k < 4; ++k) {
        int idx = (w0 + ty + k) * 128 + h0 + tx;
        tile[ty + k][tx] = s0[idx] + s1[idx] + s2[idx] + s3[idx];
    }
    __syncthreads();
    float* d = out + n * HWX;
    #pragma unroll
    for (int k = 0; k < 4; ++k)
        d[(h0 + ty + k) * 128 + w0 + tx] = tile[tx][ty + k];
}

// ===========================================================================
extern "C" void kernel_launch(void* const* d_in, const int* in_sizes, int n_in,
                              void* d_out, int out_size)
{
    const float* x  = (const float*)d_in[0];
    const float* y  = (const float*)d_in[1];
    const float* Wc = (const float*)d_in[2];
    const float* bc = (const float*)d_in[3];
    const float* gm = (const float*)d_in[4];
    float* out = (float*)d_out;

    const int ROWSMEM = 13440 * 4;  // 53760 B
    const int COLSMEM = 20800 * 4;  // 83200 B
    cudaFuncSetAttribute(row_scan_kernel,
                         cudaFuncAttributeMaxDynamicSharedMemorySize, ROWSMEM);
    cudaFuncSetAttribute(col_scan_kernel,
                         cudaFuncAttributeMaxDynamicSharedMemorySize, COLSMEM);

    row_scan_kernel<<<dim3(8, 8, 2), 128, ROWSMEM>>>(x, y, Wc, bc);
    transpose3_kernel<<<dim3(4, 4, 1536), 256>>>(y);
    col_scan_kernel<<<dim3(4, 8, 4), 256, COLSMEM>>>(Wc, bc, gm);
    sum_transpose_kernel<<<dim3(4, 4, 512), 256>>>(out);

    (void)in_sizes; (void)n_in; (void)out_size;
}